// round 10
// baseline (speedup 1.0000x reference)
#include <cuda_runtime.h>
#include <cstdint>

// ============================================================================
// FarthestSubsample: B=16, Cc=3, Cv=64, N=8192, npoint=4096 (DS_FRAC=0.5)
//
// Init PRNG (validated R7/R8): k2 = threefry_block(key(42),(0,1));
//   farthest0[b] = ((o0^o1)(k2,(0,b))) & 8191.
// Distance arithmetic V2 (R10): LLVM contraction of the XLA sum emits
//   d = fma(dz,dz, fma(dx,dx, dy*dy))
// (first operand of the first fadd gets fused; zero-init folded away).
//
// fps_kernel: 1 CTA per batch, 1024 threads, 8 pts/thread.
// gather_kernel: out = [new_coords (16,3,4096)] ++ [new_values (16,64,4096)].
// ============================================================================

#define BATCH   16
#define NPTS    8192
#define NPOINT  4096
#define NTHREADS 1024
#define PPT     (NPTS / NTHREADS)

static inline uint32_t rotl32(uint32_t x, uint32_t r) { return (x << r) | (x >> (32 - r)); }

static void tf2x32_block(uint32_t k0, uint32_t k1, uint32_t x0, uint32_t x1,
                         uint32_t* o0, uint32_t* o1) {
    const uint32_t rA[4] = {13, 15, 26, 6};
    const uint32_t rB[4] = {17, 29, 16, 24};
    uint32_t ks0 = k0, ks1 = k1, ks2 = k0 ^ k1 ^ 0x1BD11BDAu;
    x0 += ks0; x1 += ks1;
    for (int i = 0; i < 4; i++) { x0 += x1; x1 = rotl32(x1, rA[i]); x1 ^= x0; }
    x0 += ks1; x1 += ks2 + 1u;
    for (int i = 0; i < 4; i++) { x0 += x1; x1 = rotl32(x1, rB[i]); x1 ^= x0; }
    x0 += ks2; x1 += ks0 + 2u;
    for (int i = 0; i < 4; i++) { x0 += x1; x1 = rotl32(x1, rA[i]); x1 ^= x0; }
    x0 += ks0; x1 += ks1 + 3u;
    for (int i = 0; i < 4; i++) { x0 += x1; x1 = rotl32(x1, rB[i]); x1 ^= x0; }
    x0 += ks1; x1 += ks2 + 4u;
    for (int i = 0; i < 4; i++) { x0 += x1; x1 = rotl32(x1, rA[i]); x1 ^= x0; }
    x0 += ks2; x1 += ks0 + 5u;
    *o0 = x0; *o1 = x1;
}

struct Cfg { int v[BATCH]; };

static void build_config(Cfg* cfg) {
    const uint32_t K0 = 0u, K1 = 42u;            // jax.random.key(42)
    uint32_t k2a, k2b;
    tf2x32_block(K0, K1, 0u, 1u, &k2a, &k2b);    // k2 = split child 1
    for (int b = 0; b < BATCH; b++) {
        uint32_t o0, o1;
        tf2x32_block(k2a, k2b, 0u, (uint32_t)b, &o0, &o1);
        cfg->v[b] = (int)((o0 ^ o1) & (NPTS - 1));
    }
}

__device__ int g_idx[BATCH * NPOINT];

__global__ __launch_bounds__(NTHREADS, 1)
void fps_kernel(const float* __restrict__ coords, Cfg cfg) {
    extern __shared__ float smem[];
    float* sx  = smem;
    float* sy  = smem + NPTS;
    float* sz  = smem + 2 * NPTS;
    float* swv = smem + 3 * NPTS;
    int*   swi = (int*)(smem + 3 * NPTS + 32);
    int*   swin = (int*)(smem + 3 * NPTS + 64);

    const int b    = blockIdx.x;
    const int tid  = threadIdx.x;
    const int lane = tid & 31;
    const int warp = tid >> 5;
    const float* cb = coords + (size_t)b * 3 * NPTS;

    float px[PPT], py[PPT], pz[PPT], dist[PPT];
#pragma unroll
    for (int j = 0; j < PPT; j++) {
        int n = tid + j * NTHREADS;
        px[j] = cb[n];
        py[j] = cb[NPTS + n];
        pz[j] = cb[2 * NPTS + n];
        sx[n] = px[j]; sy[n] = py[j]; sz[n] = pz[j];
        dist[j] = 1e10f;
    }
    __syncthreads();

    int farthest = cfg.v[b];

    for (int t = 0; t < NPOINT; t++) {
        if (tid == 0) g_idx[b * NPOINT + t] = farthest;

        const float cx = sx[farthest], cy = sy[farthest], cz = sz[farthest];

        // V2 contraction: d = fma(dz,dz, fma(dx,dx, dy*dy))
        float bv = -1.0f; int bi = 0;
#pragma unroll
        for (int j = 0; j < PPT; j++) {
            float dx = px[j] - cx, dy = py[j] - cy, dz = pz[j] - cz;
            float d = __fmaf_rn(dz, dz, __fmaf_rn(dx, dx, __fmul_rn(dy, dy)));
            float nd = fminf(dist[j], d);
            dist[j] = nd;
            if (nd > bv) { bv = nd; bi = tid + j * NTHREADS; }
        }

        // Warp argmax (first-occurrence tie-break: smaller index wins on equal)
#pragma unroll
        for (int off = 16; off > 0; off >>= 1) {
            float v2 = __shfl_down_sync(0xffffffffu, bv, off);
            int   i2 = __shfl_down_sync(0xffffffffu, bi, off);
            if (v2 > bv || (v2 == bv && i2 < bi)) { bv = v2; bi = i2; }
        }
        if (lane == 0) { swv[warp] = bv; swi[warp] = bi; }
        __syncthreads();

        if (warp == 0) {
            bv = swv[lane]; bi = swi[lane];
#pragma unroll
            for (int off = 16; off > 0; off >>= 1) {
                float v2 = __shfl_down_sync(0xffffffffu, bv, off);
                int   i2 = __shfl_down_sync(0xffffffffu, bi, off);
                if (v2 > bv || (v2 == bv && i2 < bi)) { bv = v2; bi = i2; }
            }
            if (lane == 0) *swin = bi;
        }
        __syncthreads();
        farthest = *swin;
    }
}

#define CO (BATCH * 3 * NPOINT)
#define VO (BATCH * 64 * NPOINT)

__global__ void gather_kernel(const float* __restrict__ coords,
                              const float* __restrict__ values,
                              float* __restrict__ out) {
    int e = blockIdx.x * blockDim.x + threadIdx.x;
    if (e < CO) {
        int i = e & (NPOINT - 1);
        int c = (e >> 12) % 3;
        int b = e / (3 * NPOINT);
        int n = g_idx[b * NPOINT + i];
        out[e] = coords[((size_t)b * 3 + c) * NPTS + n];
    } else if (e < CO + VO) {
        int e2 = e - CO;
        int i = e2 & (NPOINT - 1);
        int c = (e2 >> 12) & 63;
        int b = e2 / (64 * NPOINT);
        int n = g_idx[b * NPOINT + i];
        out[e] = values[((size_t)b * 64 + c) * NPTS + n];
    }
}

extern "C" void kernel_launch(void* const* d_in, const int* in_sizes, int n_in,
                              void* d_out, int out_size) {
    const float* coords = (const float*)d_in[0];
    const float* values = (const float*)d_in[1];
    float* out = (float*)d_out;

    Cfg cfg;
    build_config(&cfg);

    const int smem_bytes = (3 * NPTS + 72) * (int)sizeof(float);
    cudaFuncSetAttribute(fps_kernel, cudaFuncAttributeMaxDynamicSharedMemorySize,
                         smem_bytes);

    fps_kernel<<<BATCH, NTHREADS, smem_bytes>>>(coords, cfg);

    const int total = CO + VO;
    gather_kernel<<<(total + 255) / 256, 256>>>(coords, values, out);
}

// round 11
// speedup vs baseline: 1.0387x; 1.0387x over previous
#include <cuda_runtime.h>
#include <cstdint>

// ============================================================================
// FarthestSubsample: B=16, Cc=3, Cv=64, N=8192, npoint=4096
//
// R11: cluster-parallel FPS. 4 CTAs per batch (cluster 4), 256 thr/CTA,
// 8 pts/thread in registers. Per-step global argmax via DSMEM mailboxes
// (release-store winner to all ranks, acquire-spin on 4 local slots,
// parity double-buffered, symmetric combine). Warp argmax via redux.sync.
//
// Validated invariants kept bit-exact:
//   init: k2=threefry(key(42),(0,1)); farthest0[b]=((o0^o1)(k2,(0,b)))&8191
//   dist: d = fma(dz,dz, fma(dx,dx, dy*dy)); argmax first-occurrence
// Output: [new_coords (16,3,4096)] ++ [new_values (16,64,4096)]
// ============================================================================

#define BATCH    16
#define NPTS     8192
#define NPOINT   4096
#define CLUSTER  4
#define THREADS  256
#define LPTS     (NPTS / CLUSTER)     // 2048 points per CTA
#define PPT      (LPTS / THREADS)     // 8 points per thread

static inline uint32_t rotl32(uint32_t x, uint32_t r) { return (x << r) | (x >> (32 - r)); }

static void tf2x32_block(uint32_t k0, uint32_t k1, uint32_t x0, uint32_t x1,
                         uint32_t* o0, uint32_t* o1) {
    const uint32_t rA[4] = {13, 15, 26, 6};
    const uint32_t rB[4] = {17, 29, 16, 24};
    uint32_t ks0 = k0, ks1 = k1, ks2 = k0 ^ k1 ^ 0x1BD11BDAu;
    x0 += ks0; x1 += ks1;
    for (int i = 0; i < 4; i++) { x0 += x1; x1 = rotl32(x1, rA[i]); x1 ^= x0; }
    x0 += ks1; x1 += ks2 + 1u;
    for (int i = 0; i < 4; i++) { x0 += x1; x1 = rotl32(x1, rB[i]); x1 ^= x0; }
    x0 += ks2; x1 += ks0 + 2u;
    for (int i = 0; i < 4; i++) { x0 += x1; x1 = rotl32(x1, rA[i]); x1 ^= x0; }
    x0 += ks0; x1 += ks1 + 3u;
    for (int i = 0; i < 4; i++) { x0 += x1; x1 = rotl32(x1, rB[i]); x1 ^= x0; }
    x0 += ks1; x1 += ks2 + 4u;
    for (int i = 0; i < 4; i++) { x0 += x1; x1 = rotl32(x1, rA[i]); x1 ^= x0; }
    x0 += ks2; x1 += ks0 + 5u;
    *o0 = x0; *o1 = x1;
}

struct Cfg { int v[BATCH]; };

static void build_config(Cfg* cfg) {
    uint32_t k2a, k2b;
    tf2x32_block(0u, 42u, 0u, 1u, &k2a, &k2b);
    for (int b = 0; b < BATCH; b++) {
        uint32_t o0, o1;
        tf2x32_block(k2a, k2b, 0u, (uint32_t)b, &o0, &o1);
        cfg->v[b] = (int)((o0 ^ o1) & (NPTS - 1));
    }
}

__device__ int g_idx[BATCH * NPOINT];

// ---- cluster PTX helpers ----
__device__ __forceinline__ uint32_t smem_u32(const void* p) {
    uint32_t a;
    asm("{ .reg .u64 t; cvta.to.shared.u64 t, %1; cvt.u32.u64 %0, t; }"
        : "=r"(a) : "l"(p));
    return a;
}
__device__ __forceinline__ uint32_t mapa_u32(uint32_t addr, uint32_t rank) {
    uint32_t r;
    asm("mapa.shared::cluster.u32 %0, %1, %2;" : "=r"(r) : "r"(addr), "r"(rank));
    return r;
}
__device__ __forceinline__ void st_rel_cluster_u64(uint32_t addr, unsigned long long v) {
    asm volatile("st.release.cluster.shared::cluster.u64 [%0], %1;"
                 :: "r"(addr), "l"(v) : "memory");
}
__device__ __forceinline__ unsigned long long ld_acq_u64(uint32_t addr) {
    unsigned long long v;
    asm volatile("ld.acquire.cluster.shared::cta.u64 %0, [%1];"
                 : "=l"(v) : "r"(addr) : "memory");
    return v;
}

__global__ __launch_bounds__(THREADS, 1) __cluster_dims__(CLUSTER, 1, 1)
void fps_kernel(const float* __restrict__ coords, Cfg cfg) {
    extern __shared__ float smem[];
    float* sx = smem;                          // NPTS (full coords copy)
    float* sy = smem + NPTS;
    float* sz = smem + 2 * NPTS;
    unsigned long long* swarp = (unsigned long long*)(smem + 3 * NPTS);  // 8
    unsigned long long* mbox  = swarp + 8;     // 8: [parity*4 + rank]
    int* swin = (int*)(mbox + 8);

    const int b   = blockIdx.x / CLUSTER;
    uint32_t rank; asm("mov.u32 %0, %%cluster_ctarank;" : "=r"(rank));
    const int tid  = threadIdx.x;
    const int lane = tid & 31;
    const int warp = tid >> 5;
    const float* cb = coords + (size_t)b * 3 * NPTS;

    // Full coords copy (for centroid lookup by global index)
    for (int i = tid; i < NPTS; i += THREADS) {
        sx[i] = cb[i]; sy[i] = cb[NPTS + i]; sz[i] = cb[2 * NPTS + i];
    }
    // Register-resident slice
    const int gbase = (int)rank * LPTS;
    float px[PPT], py[PPT], pz[PPT], dist[PPT];
#pragma unroll
    for (int j = 0; j < PPT; j++) {
        int g = gbase + tid + j * THREADS;
        px[j] = cb[g]; py[j] = cb[NPTS + g]; pz[j] = cb[2 * NPTS + g];
        dist[j] = 1e10f;
    }
    if (tid < 8) mbox[tid] = 0ull;             // tag 0 != any expected (>=1)
    __syncthreads();
    asm volatile("barrier.cluster.arrive.aligned;" ::: "memory");
    asm volatile("barrier.cluster.wait.aligned;" ::: "memory");

    const uint32_t mb_local = smem_u32(mbox);
    uint32_t peer_mb[CLUSTER];
#pragma unroll
    for (int r = 0; r < CLUSTER; r++) peer_mb[r] = mapa_u32(mb_local, (uint32_t)r);

    int farthest = cfg.v[b];

    for (int t = 0; t < NPOINT; t++) {
        if (rank == 0 && tid == 0) g_idx[b * NPOINT + t] = farthest;

        const float cx = sx[farthest], cy = sy[farthest], cz = sz[farthest];

        // Bit-exact distance: d = fma(dz,dz, fma(dx,dx, dy*dy))
        float bv = -1.0f; int bi = 0;
#pragma unroll
        for (int j = 0; j < PPT; j++) {
            float dx = px[j] - cx, dy = py[j] - cy, dz = pz[j] - cz;
            float d = __fmaf_rn(dz, dz, __fmaf_rn(dx, dx, __fmul_rn(dy, dy)));
            float nd = fminf(dist[j], d);
            dist[j] = nd;
            if (nd > bv) { bv = nd; bi = gbase + tid + j * THREADS; }
        }

        // Warp argmax via redux (dist >= 0 so float bits are monotone)
        uint32_t fb   = __float_as_uint(bv);
        uint32_t wmax = __reduce_max_sync(0xffffffffu, fb);
        uint32_t cand = (fb == wmax) ? (uint32_t)bi : 0xffffffffu;
        uint32_t widx = __reduce_min_sync(0xffffffffu, cand);
        if (lane == 0)
            swarp[warp] = ((unsigned long long)wmax << 32)
                        | (unsigned long long)(NPTS - 1 - widx);
        __syncthreads();

        if (tid == 0) {
            // CTA winner = max packed key over 8 warps
            unsigned long long best = swarp[0];
#pragma unroll
            for (int w = 1; w < 8; w++) { unsigned long long v = swarp[w]; if (v > best) best = v; }
            uint32_t cfb  = (uint32_t)(best >> 32);
            uint32_t cidx = (uint32_t)(NPTS - 1) - (uint32_t)(best & 0xffffffffu);

            // Send {fbits, idx, tag} to slot[myrank] of every CTA's mailbox
            unsigned long long tw = ((unsigned long long)cfb << 32)
                                  | ((unsigned long long)cidx << 13)
                                  | (unsigned long long)((t + 1) & 0x1fff);
            uint32_t slot_off = (uint32_t)(((t & 1) * 4 + (int)rank) * 8);
#pragma unroll
            for (int r = 0; r < CLUSTER; r++) st_rel_cluster_u64(peer_mb[r] + slot_off, tw);

            // Receive all 4 winners (parity-buffered, tag-matched), combine
            const uint32_t expect = (uint32_t)((t + 1) & 0x1fff);
            unsigned long long bestkey = 0ull;
#pragma unroll
            for (int r = 0; r < CLUSTER; r++) {
                uint32_t a = mb_local + (uint32_t)(((t & 1) * 4 + r) * 8);
                unsigned long long v;
                do { v = ld_acq_u64(a); } while ((uint32_t)(v & 0x1fff) != expect);
                uint32_t fbr = (uint32_t)(v >> 32);
                uint32_t ixr = (uint32_t)((v >> 13) & 0x1fff);
                unsigned long long key = ((unsigned long long)fbr << 32)
                                       | (unsigned long long)(NPTS - 1 - ixr);
                if (key > bestkey) bestkey = key;
            }
            *swin = (int)(NPTS - 1) - (int)(bestkey & 0xffffffffu);
        }
        __syncthreads();
        farthest = *swin;
    }

    asm volatile("barrier.cluster.arrive.aligned;" ::: "memory");
    asm volatile("barrier.cluster.wait.aligned;" ::: "memory");
}

#define CO (BATCH * 3 * NPOINT)
#define VO (BATCH * 64 * NPOINT)

__global__ void gather_kernel(const float* __restrict__ coords,
                              const float* __restrict__ values,
                              float* __restrict__ out) {
    int e = blockIdx.x * blockDim.x + threadIdx.x;
    if (e < CO) {
        int i = e & (NPOINT - 1);
        int c = (e >> 12) % 3;
        int b = e / (3 * NPOINT);
        int n = g_idx[b * NPOINT + i];
        out[e] = coords[((size_t)b * 3 + c) * NPTS + n];
    } else if (e < CO + VO) {
        int e2 = e - CO;
        int i = e2 & (NPOINT - 1);
        int c = (e2 >> 12) & 63;
        int b = e2 / (64 * NPOINT);
        int n = g_idx[b * NPOINT + i];
        out[e] = values[((size_t)b * 64 + c) * NPTS + n];
    }
}

extern "C" void kernel_launch(void* const* d_in, const int* in_sizes, int n_in,
                              void* d_out, int out_size) {
    const float* coords = (const float*)d_in[0];
    const float* values = (const float*)d_in[1];
    float* out = (float*)d_out;

    Cfg cfg;
    build_config(&cfg);

    const int smem_bytes = 3 * NPTS * 4 + 8 * 8 + 8 * 8 + 16;
    cudaFuncSetAttribute(fps_kernel, cudaFuncAttributeMaxDynamicSharedMemorySize,
                         smem_bytes);

    fps_kernel<<<BATCH * CLUSTER, THREADS, smem_bytes>>>(coords, cfg);

    const int total = CO + VO;
    gather_kernel<<<(total + 255) / 256, 256>>>(coords, values, out);
}

// round 13
// speedup vs baseline: 1.1601x; 1.1169x over previous
#include <cuda_runtime.h>
#include <cstdint>

// ============================================================================
// FarthestSubsample: B=16, Cc=3, Cv=64, N=8192, npoint=4096
//
// R13 = R12 with the deadlock fixed: the post-spin butterfly among lanes 0-3
// used mask 0xffffffff while lanes 4-31 never reached it (sync-shuffle waits
// for all masked lanes -> hang). Mask is now 0xf.
//
//   - 4 CTAs/batch (cluster 4), 256 thr/CTA, 8 pts/thread, f32x2 packed math.
//   - warp stage: redux.sync; CTA stage: warp0 bfly over 8 warp keys;
//     cluster stage: lanes0-3 parallel DSMEM send + parallel acquire-spin.
// Bit-exact invariants (validated R7-R11):
//   init: k2=threefry(key(42),(0,1)); farthest0[b]=((o0^o1)(k2,(0,b)))&8191
//   dist: d = fma(dz,dz, fma(dx,dx, dy*dy)); argmax first-occurrence.
// Output: [new_coords (16,3,4096)] ++ [new_values (16,64,4096)]
// ============================================================================

#define BATCH    16
#define NPTS     8192
#define NPOINT   4096
#define CLUSTER  4
#define THREADS  256
#define LPTS     (NPTS / CLUSTER)     // 2048
#define PPT      (LPTS / THREADS)     // 8
#define NPAIR    (PPT / 2)            // 4

static inline uint32_t rotl32(uint32_t x, uint32_t r) { return (x << r) | (x >> (32 - r)); }

static void tf2x32_block(uint32_t k0, uint32_t k1, uint32_t x0, uint32_t x1,
                         uint32_t* o0, uint32_t* o1) {
    const uint32_t rA[4] = {13, 15, 26, 6};
    const uint32_t rB[4] = {17, 29, 16, 24};
    uint32_t ks0 = k0, ks1 = k1, ks2 = k0 ^ k1 ^ 0x1BD11BDAu;
    x0 += ks0; x1 += ks1;
    for (int i = 0; i < 4; i++) { x0 += x1; x1 = rotl32(x1, rA[i]); x1 ^= x0; }
    x0 += ks1; x1 += ks2 + 1u;
    for (int i = 0; i < 4; i++) { x0 += x1; x1 = rotl32(x1, rB[i]); x1 ^= x0; }
    x0 += ks2; x1 += ks0 + 2u;
    for (int i = 0; i < 4; i++) { x0 += x1; x1 = rotl32(x1, rA[i]); x1 ^= x0; }
    x0 += ks0; x1 += ks1 + 3u;
    for (int i = 0; i < 4; i++) { x0 += x1; x1 = rotl32(x1, rB[i]); x1 ^= x0; }
    x0 += ks1; x1 += ks2 + 4u;
    for (int i = 0; i < 4; i++) { x0 += x1; x1 = rotl32(x1, rA[i]); x1 ^= x0; }
    x0 += ks2; x1 += ks0 + 5u;
    *o0 = x0; *o1 = x1;
}

struct Cfg { int v[BATCH]; };

static void build_config(Cfg* cfg) {
    uint32_t k2a, k2b;
    tf2x32_block(0u, 42u, 0u, 1u, &k2a, &k2b);
    for (int b = 0; b < BATCH; b++) {
        uint32_t o0, o1;
        tf2x32_block(k2a, k2b, 0u, (uint32_t)b, &o0, &o1);
        cfg->v[b] = (int)((o0 ^ o1) & (NPTS - 1));
    }
}

__device__ int g_idx[BATCH * NPOINT];

// ---- PTX helpers ----
__device__ __forceinline__ uint32_t smem_u32(const void* p) {
    uint32_t a;
    asm("{ .reg .u64 t; cvta.to.shared.u64 t, %1; cvt.u32.u64 %0, t; }"
        : "=r"(a) : "l"(p));
    return a;
}
__device__ __forceinline__ uint32_t mapa_u32(uint32_t addr, uint32_t rank) {
    uint32_t r;
    asm("mapa.shared::cluster.u32 %0, %1, %2;" : "=r"(r) : "r"(addr), "r"(rank));
    return r;
}
__device__ __forceinline__ void st_rel_cluster_u64(uint32_t addr, unsigned long long v) {
    asm volatile("st.release.cluster.shared::cluster.u64 [%0], %1;"
                 :: "r"(addr), "l"(v) : "memory");
}
__device__ __forceinline__ unsigned long long ld_acq_u64(uint32_t addr) {
    unsigned long long v;
    asm volatile("ld.acquire.cluster.shared::cta.u64 %0, [%1];"
                 : "=l"(v) : "r"(addr) : "memory");
    return v;
}
// packed f32x2 (per-lane rounding identical to scalar rn ops)
__device__ __forceinline__ unsigned long long pack2(float lo, float hi) {
    unsigned long long r;
    asm("mov.b64 %0, {%1, %2};" : "=l"(r) : "f"(lo), "f"(hi));
    return r;
}
__device__ __forceinline__ void unpack2(unsigned long long v, float& lo, float& hi) {
    asm("mov.b64 {%0, %1}, %2;" : "=f"(lo), "=f"(hi) : "l"(v));
}
__device__ __forceinline__ unsigned long long add2(unsigned long long a, unsigned long long b) {
    unsigned long long r; asm("add.rn.f32x2 %0, %1, %2;" : "=l"(r) : "l"(a), "l"(b)); return r;
}
__device__ __forceinline__ unsigned long long mul2(unsigned long long a, unsigned long long b) {
    unsigned long long r; asm("mul.rn.f32x2 %0, %1, %2;" : "=l"(r) : "l"(a), "l"(b)); return r;
}
__device__ __forceinline__ unsigned long long fma2(unsigned long long a, unsigned long long b,
                                                   unsigned long long c) {
    unsigned long long r; asm("fma.rn.f32x2 %0, %1, %2, %3;" : "=l"(r) : "l"(a), "l"(b), "l"(c)); return r;
}

__global__ __launch_bounds__(THREADS, 1) __cluster_dims__(CLUSTER, 1, 1)
void fps_kernel(const float* __restrict__ coords, Cfg cfg) {
    extern __shared__ float smem[];
    float* sx = smem;                          // NPTS
    float* sy = smem + NPTS;
    float* sz = smem + 2 * NPTS;
    unsigned long long* swarp = (unsigned long long*)(smem + 3 * NPTS);  // 8
    unsigned long long* mbox  = swarp + 8;     // 8 slots [parity*4 + senderRank]
    int* swin = (int*)(mbox + 8);

    const int b   = blockIdx.x / CLUSTER;
    uint32_t rank; asm("mov.u32 %0, %%cluster_ctarank;" : "=r"(rank));
    const int tid  = threadIdx.x;
    const int lane = tid & 31;
    const int warp = tid >> 5;
    const float* cb = coords + (size_t)b * 3 * NPTS;

    for (int i = tid; i < NPTS; i += THREADS) {
        sx[i] = cb[i]; sy[i] = cb[NPTS + i]; sz[i] = cb[2 * NPTS + i];
    }
    const int gbase = (int)rank * LPTS;
    unsigned long long p2x[NPAIR], p2y[NPAIR], p2z[NPAIR];
    float dist[PPT];
#pragma unroll
    for (int k = 0; k < NPAIR; k++) {
        int g0 = gbase + tid + (2 * k) * THREADS;
        int g1 = gbase + tid + (2 * k + 1) * THREADS;
        p2x[k] = pack2(cb[g0], cb[g1]);
        p2y[k] = pack2(cb[NPTS + g0], cb[NPTS + g1]);
        p2z[k] = pack2(cb[2 * NPTS + g0], cb[2 * NPTS + g1]);
        dist[2 * k] = 1e10f; dist[2 * k + 1] = 1e10f;
    }
    if (tid < 8) mbox[tid] = 0ull;
    __syncthreads();
    asm volatile("barrier.cluster.arrive.aligned;" ::: "memory");
    asm volatile("barrier.cluster.wait.aligned;" ::: "memory");

    const uint32_t mb_local = smem_u32(mbox);
    uint32_t peer_addr = (lane < CLUSTER) ? mapa_u32(mb_local, (uint32_t)lane) : 0u;

    int farthest = cfg.v[b];

    for (int t = 0; t < NPOINT; t++) {
        if (rank == 0 && tid == 0) g_idx[b * NPOINT + t] = farthest;

        const float cx = sx[farthest], cy = sy[farthest], cz = sz[farthest];
        const unsigned long long ncx = pack2(-cx, -cx);
        const unsigned long long ncy = pack2(-cy, -cy);
        const unsigned long long ncz = pack2(-cz, -cz);

        float bv = -1.0f; int bi = 0;
#pragma unroll
        for (int k = 0; k < NPAIR; k++) {
            unsigned long long dx = add2(p2x[k], ncx);
            unsigned long long dy = add2(p2y[k], ncy);
            unsigned long long dz = add2(p2z[k], ncz);
            // d = fma(dz,dz, fma(dx,dx, dy*dy))  (bit-exact V2, per lane)
            unsigned long long d2 = fma2(dz, dz, fma2(dx, dx, mul2(dy, dy)));
            float dlo, dhi; unpack2(d2, dlo, dhi);
            float n0 = fminf(dist[2 * k], dlo);
            float n1 = fminf(dist[2 * k + 1], dhi);
            dist[2 * k] = n0; dist[2 * k + 1] = n1;
            if (n0 > bv) { bv = n0; bi = gbase + tid + (2 * k) * THREADS; }
            if (n1 > bv) { bv = n1; bi = gbase + tid + (2 * k + 1) * THREADS; }
        }

        // warp argmax via redux (dist >= 0 -> float bits monotone)
        uint32_t fb   = __float_as_uint(bv);
        uint32_t wmax = __reduce_max_sync(0xffffffffu, fb);
        uint32_t cand = (fb == wmax) ? (uint32_t)bi : 0xffffffffu;
        uint32_t widx = __reduce_min_sync(0xffffffffu, cand);
        const uint32_t tag = (uint32_t)((t + 1) & 0x1fff);
        if (lane == 0) {
            // key = {fbits at [26:58) | invidx at [13:26) | tag at [0:13)}
            swarp[warp] = ((unsigned long long)wmax << 26)
                        | ((unsigned long long)(NPTS - 1 - widx) << 13)
                        | (unsigned long long)tag;
        }
        __syncthreads();

        if (warp == 0) {
            // CTA combine: all 32 lanes run the bfly over 8 warp keys
            unsigned long long key = swarp[lane & 7];
#pragma unroll
            for (int off = 4; off > 0; off >>= 1) {
                unsigned long long o = __shfl_xor_sync(0xffffffffu, key, off);
                if (o > key) key = o;
            }
            // cluster exchange: lanes 0-3 only; masks restricted to 0xf
            uint32_t my_slot_off   = (uint32_t)(((t & 1) * CLUSTER + (int)rank) * 8);
            uint32_t poll_slot_off = (uint32_t)(((t & 1) * CLUSTER + lane) * 8);
            if (lane < CLUSTER) {
                st_rel_cluster_u64(peer_addr + my_slot_off, key);
                unsigned long long v;
                uint32_t a = mb_local + poll_slot_off;
                do { v = ld_acq_u64(a); } while ((uint32_t)(v & 0x1fff) != tag);
                key = v;
#pragma unroll
                for (int off = 2; off > 0; off >>= 1) {
                    unsigned long long o = __shfl_xor_sync(0x0000000fu, key, off);
                    if (o > key) key = o;
                }
                if (lane == 0)
                    *swin = (int)(NPTS - 1) - (int)((key >> 13) & 0x1fff);
            }
        }
        __syncthreads();
        farthest = *swin;
    }

    asm volatile("barrier.cluster.arrive.aligned;" ::: "memory");
    asm volatile("barrier.cluster.wait.aligned;" ::: "memory");
}

#define CO (BATCH * 3 * NPOINT)
#define VO (BATCH * 64 * NPOINT)

__global__ void gather_kernel(const float* __restrict__ coords,
                              const float* __restrict__ values,
                              float* __restrict__ out) {
    int e = blockIdx.x * blockDim.x + threadIdx.x;
    if (e < CO) {
        int i = e & (NPOINT - 1);
        int c = (e >> 12) % 3;
        int b = e / (3 * NPOINT);
        int n = g_idx[b * NPOINT + i];
        out[e] = coords[((size_t)b * 3 + c) * NPTS + n];
    } else if (e < CO + VO) {
        int e2 = e - CO;
        int i = e2 & (NPOINT - 1);
        int c = (e2 >> 12) & 63;
        int b = e2 / (64 * NPOINT);
        int n = g_idx[b * NPOINT + i];
        out[e] = values[((size_t)b * 64 + c) * NPTS + n];
    }
}

// Launch-order shim so ncu (-s 5 -c 1) can land on fps_kernel.
__global__ void noop_kernel() {}

extern "C" void kernel_launch(void* const* d_in, const int* in_sizes, int n_in,
                              void* d_out, int out_size) {
    const float* coords = (const float*)d_in[0];
    const float* values = (const float*)d_in[1];
    float* out = (float*)d_out;

    Cfg cfg;
    build_config(&cfg);

    const int smem_bytes = 3 * NPTS * 4 + 8 * 8 + 8 * 8 + 16;
    cudaFuncSetAttribute(fps_kernel, cudaFuncAttributeMaxDynamicSharedMemorySize,
                         smem_bytes);

    noop_kernel<<<1, 32>>>();
    fps_kernel<<<BATCH * CLUSTER, THREADS, smem_bytes>>>(coords, cfg);
    gather_kernel<<<(CO + VO + 255) / 256, 256>>>(coords, values, out);
    noop_kernel<<<1, 32>>>();
}